// round 6
// baseline (speedup 1.0000x reference)
#include <cuda_runtime.h>

// ConvolutionalCapsule EM-routing. One CTA (512 threads) per output position.
// Votes live ONLY in registers: thread (o, i_lo, ph) owns v[r][k] for
// i = i_lo + 16r (r=0..8) and pp = 8*ph + k (k=0..7).  No vote SMEM ->
// smem ~32 KB, 16 warps/SM, all EM math is register FMA + warp shuffles.
//
// Warp w = output capsule o (16 warps). lane = i_lo*2 + ph.

#define BATCH   8
#define HW      14
#define OHW     12
#define NPOS    (BATCH * OHW * OHW)   // 1152
#define NI      144
#define RSTR    152
#define CAP_EPS 1e-9f

// SMEM floats: pose 144*20 = 2880 | rp 16*152 = 2432 | z 144*17 = 2448 | a 144
#define OFF_RP   2880
#define OFF_Z    (OFF_RP + 16*RSTR)
#define OFF_A    (OFF_Z + NI*17)
#define SMEM_FLOATS (OFF_A + NI)        // 7904
#define SMEM_BYTES  (SMEM_FLOATS * 4)   // 31616 B

__global__ __launch_bounds__(512, 1)
void capsule_em_kernel(const float* __restrict__ g_pose,
                       const float* __restrict__ g_act,
                       const float* __restrict__ g_w,
                       const float* __restrict__ g_bv,
                       const float* __restrict__ g_ba,
                       float* __restrict__ out)
{
    extern __shared__ float sm[];
    float* pose_sh = sm;              // [i*20 + 4*x + y] (float4 stride 5)
    float* rp_sm   = sm + OFF_RP;     // rr' = rr * a, [o*152 + i]
    float* z_sm    = sm + OFF_Z;      // [i*17 + o]
    float* a_sh    = sm + OFF_A;      // [i]

    const int tid  = threadIdx.x;
    const int lane = tid & 31;
    const int o    = tid >> 5;        // one warp per output capsule
    const int i_lo = lane >> 1;
    const int ph   = lane & 1;        // which half of the 16 pose elems

    const int n   = blockIdx.x;
    const int b   = n / (OHW * OHW);
    const int rem = n - b * (OHW * OHW);
    const int h0  = rem / OHW;
    const int w0  = rem - h0 * OHW;

    // ---- Stage pose tile + activations ----
    {
        const float4* gp4 = (const float4*)g_pose;
        float4* ps4 = (float4*)pose_sh;
        #pragma unroll
        for (int idx = tid; idx < 576; idx += 512) {
            int kk = idx >> 6;            // patch 0..8
            int c4 = idx & 63;            // cap*4 + x
            int di = kk / 3, dj = kk - di * 3;
            int pix = (b * HW + h0 + di) * HW + (w0 + dj);
            int cap = c4 >> 2, x = c4 & 3;
            ps4[(kk * 16 + cap) * 5 + x] = gp4[pix * 64 + c4];
        }
        if (tid < NI) {
            int kk = tid >> 4;
            int cap = tid & 15;
            int di = kk / 3, dj = kk - di * 3;
            int pix = (b * HW + h0 + di) * HW + (w0 + dj);
            a_sh[tid] = g_act[pix * 16 + cap];
        }
    }
    __syncthreads();

    // ---- rr' init + votes straight into registers ----
    // v[r*8 + (x - 2*ph)*4 + z] = sum_y pose[i][x][y] * w[i][o][y][z],
    // for x in {2ph, 2ph+1}, z = 0..3, i = i_lo + 16r.
    float v[72];
    {
        for (int idx = tid; idx < 16 * NI; idx += 512) {
            int oo = idx / NI;
            int ii = idx - oo * NI;
            rp_sm[oo * RSTR + ii] = a_sh[ii] * 0.0625f;
        }
        const float4* w4 = (const float4*)g_w;       // [i*64 + o*4 + y]
        const float4* p4 = (const float4*)pose_sh;   // [i*5 + x]
        #pragma unroll
        for (int r = 0; r < 9; r++) {
            int i = i_lo + 16 * r;
            float4 pa = p4[i * 5 + 2 * ph];          // row x = 2ph
            float4 pb = p4[i * 5 + 2 * ph + 1];      // row x = 2ph+1
            float4 wr0 = w4[i * 64 + o * 4 + 0];
            float4 wr1 = w4[i * 64 + o * 4 + 1];
            float4 wr2 = w4[i * 64 + o * 4 + 2];
            float4 wr3 = w4[i * 64 + o * 4 + 3];
            v[r*8 + 0] = pa.x*wr0.x + pa.y*wr1.x + pa.z*wr2.x + pa.w*wr3.x;
            v[r*8 + 1] = pa.x*wr0.y + pa.y*wr1.y + pa.z*wr2.y + pa.w*wr3.y;
            v[r*8 + 2] = pa.x*wr0.z + pa.y*wr1.z + pa.z*wr2.z + pa.w*wr3.z;
            v[r*8 + 3] = pa.x*wr0.w + pa.y*wr1.w + pa.z*wr2.w + pa.w*wr3.w;
            v[r*8 + 4] = pb.x*wr0.x + pb.y*wr1.x + pb.z*wr2.x + pb.w*wr3.x;
            v[r*8 + 5] = pb.x*wr0.y + pb.y*wr1.y + pb.z*wr2.y + pb.w*wr3.y;
            v[r*8 + 6] = pb.x*wr0.z + pb.y*wr1.z + pb.z*wr2.z + pb.w*wr3.z;
            v[r*8 + 7] = pb.x*wr0.w + pb.y*wr1.w + pb.z*wr2.w + pb.w*wr3.w;
        }
    }
    __syncthreads();

    // ---- EM routing ----
    const float bvo = g_bv[o];
    const float bao = g_ba[o];
    float mean[8], iv[8];
    float act = 0.0f;

    #pragma unroll 1
    for (int t = 0; t < 3; t++) {
        const float inv_temp = 1.0f + (float)t;

        // M-step: per-thread partial moments over my 9 i's
        float S0 = 0.0f, S1[8], S2[8];
        #pragma unroll
        for (int k = 0; k < 8; k++) { S1[k] = 0.0f; S2[k] = 0.0f; }
        #pragma unroll
        for (int r = 0; r < 9; r++) {
            float q = rp_sm[o * RSTR + i_lo + 16 * r];
            S0 += q;
            #pragma unroll
            for (int k = 0; k < 8; k++) {
                float vv = v[r*8 + k];
                S1[k] = fmaf(q, vv, S1[k]);
                S2[k] = fmaf(q * vv, vv, S2[k]);
            }
        }
        // reduce over the 16 i_lo lanes (lane bits 1..4)
        #pragma unroll
        for (int m = 2; m <= 16; m <<= 1) {
            S0 += __shfl_xor_sync(0xffffffffu, S0, m);
            #pragma unroll
            for (int k = 0; k < 8; k++) {
                S1[k] += __shfl_xor_sync(0xffffffffu, S1[k], m);
                S2[k] += __shfl_xor_sync(0xffffffffu, S2[k], m);
            }
        }

        float invS0 = __fdividef(1.0f, S0);
        float Lh = 0.0f;
        #pragma unroll
        for (int k = 0; k < 8; k++) {
            mean[k] = S1[k] * invS0;
            float var = fmaxf(S2[k] * invS0 - mean[k] * mean[k], 0.0f);
            float stdv = sqrtf(var);
            Lh += __logf(stdv + CAP_EPS);
            iv[k] = __fdividef(1.0f, 2.0f * var + CAP_EPS);
        }
        float L = Lh + __shfl_xor_sync(0xffffffffu, Lh, 1);

        float cost = S0 * (16.0f * bvo + L);
        act = 1.0f / (1.0f + __expf(-inv_temp * (bao - cost)));

        if (t < 2) {
            // E-step: register-only distances + one xor-1 shuffle
            float zc = __logf(act + CAP_EPS) - L;
            #pragma unroll
            for (int r = 0; r < 9; r++) {
                float s = 0.0f;
                #pragma unroll
                for (int k = 0; k < 8; k++) {
                    float d = v[r*8 + k] - mean[k];
                    s = fmaf(d * iv[k], d, s);
                }
                s += __shfl_xor_sync(0xffffffffu, s, 1);
                if (ph == 0)
                    z_sm[(i_lo + 16 * r) * 17 + o] = zc - s;
            }
            __syncthreads();

            // softmax over o per input capsule i; fold a into rr'
            if (tid < NI) {
                float zr[16];
                float zmax = -1e30f;
                #pragma unroll
                for (int oo = 0; oo < 16; oo++) {
                    zr[oo] = z_sm[tid * 17 + oo];
                    zmax = fmaxf(zmax, zr[oo]);
                }
                float se = 0.0f;
                #pragma unroll
                for (int oo = 0; oo < 16; oo++) {
                    zr[oo] = __expf(zr[oo] - zmax);
                    se += zr[oo];
                }
                float scale = __fdividef(a_sh[tid], se);
                #pragma unroll
                for (int oo = 0; oo < 16; oo++)
                    rp_sm[oo * RSTR + tid] = zr[oo] * scale;
            }
            __syncthreads();
        }
    }

    // ---- Outputs: pose [N,16,4,4] then activation [N,16] ----
    if (i_lo == 0) {
        #pragma unroll
        for (int k = 0; k < 8; k++)
            out[n * 256 + o * 16 + 8 * ph + k] = mean[k];
        if (ph == 0)
            out[NPOS * 256 + n * 16 + o] = act;
    }
}

extern "C" void kernel_launch(void* const* d_in, const int* in_sizes, int n_in,
                              void* d_out, int out_size)
{
    const float* g_pose = (const float*)d_in[0];
    const float* g_act  = (const float*)d_in[1];
    const float* g_w    = (const float*)d_in[2];
    const float* g_bv   = (const float*)d_in[3];
    const float* g_ba   = (const float*)d_in[4];
    float* out = (float*)d_out;

    cudaFuncSetAttribute(capsule_em_kernel,
                         cudaFuncAttributeMaxDynamicSharedMemorySize, SMEM_BYTES);
    capsule_em_kernel<<<NPOS, 512, SMEM_BYTES>>>(g_pose, g_act, g_w, g_bv, g_ba, out);
}